// round 1
// baseline (speedup 1.0000x reference)
#include <cuda_runtime.h>
#include <math.h>

#define NN 100000
#define NE 3200000
#define NGR 64
static __device__ __constant__ float AVG_LOG_C = 3.4965076f; // log(33.0)

// ---------------- scratch (device globals; no allocations) ----------------
__device__ int   g_cnt[NN];
__device__ int   g_fill[NN];
__device__ int   g_rowstart[NN];
__device__ int   g_bsum[512];
__device__ int   g_boff[512];
__device__ int   g_srt[NE];
__device__ float g_s1[NN];
__device__ float g_s2[NN];
__device__ float g_hA[NN * 96];
__device__ float g_hB[NN * 96];
__device__ float g_agg[NN * 384];
__device__ float g_bnsum[128];
__device__ float g_bnssq[128];
__device__ float g_scale[128];
__device__ float g_shift[128];
__device__ float g_zsum[NGR * 20];
__device__ int   g_gcnt[NGR];

// ---------------- graph preprocessing ----------------
__global__ void k_zero() {
    int i = blockIdx.x * 256 + threadIdx.x;
    if (i < NN) { g_cnt[i] = 0; g_fill[i] = 0; }
    if (i < NGR * 20) g_zsum[i] = 0.f;
    if (i < NGR) g_gcnt[i] = 0;
}

__global__ void k_count(const int* __restrict__ dst) {
    int i = blockIdx.x * 256 + threadIdx.x;
    if (i < NE) atomicAdd(&g_cnt[dst[i]], 1);
}

__global__ void k_scan1() {
    __shared__ int s[256];
    int tid = threadIdx.x;
    int i = blockIdx.x * 256 + tid;
    s[tid] = (i < NN) ? g_cnt[i] : 0;
    __syncthreads();
    for (int off = 128; off > 0; off >>= 1) {
        if (tid < off) s[tid] += s[tid + off];
        __syncthreads();
    }
    if (tid == 0) g_bsum[blockIdx.x] = s[0];
}

__global__ void k_scan2() {
    __shared__ int s[512];
    int tid = threadIdx.x;
    int v = (tid < 391) ? g_bsum[tid] : 0;
    s[tid] = v;
    __syncthreads();
    for (int off = 1; off < 512; off <<= 1) {
        int t = (tid >= off) ? s[tid - off] : 0;
        __syncthreads();
        s[tid] += t;
        __syncthreads();
    }
    g_boff[tid] = s[tid] - v;
}

__global__ void k_scan3() {
    __shared__ int s[256];
    int tid = threadIdx.x;
    int i = blockIdx.x * 256 + tid;
    int v = (i < NN) ? g_cnt[i] : 0;
    s[tid] = v;
    __syncthreads();
    for (int off = 1; off < 256; off <<= 1) {
        int t = (tid >= off) ? s[tid - off] : 0;
        __syncthreads();
        s[tid] += t;
        __syncthreads();
    }
    if (i < NN) g_rowstart[i] = g_boff[blockIdx.x] + s[tid] - v;
}

__global__ void k_scatter(const int* __restrict__ src, const int* __restrict__ dst) {
    int i = blockIdx.x * 256 + threadIdx.x;
    if (i < NE) {
        int d = dst[i];
        int p = g_rowstart[d] + atomicAdd(&g_fill[d], 1);
        g_srt[p] = src[i];
    }
}

__global__ void k_prep() {
    int i = blockIdx.x * 256 + threadIdx.x;
    if (i < NN) {
        int deg = g_cnt[i];
        float degc = (float)(deg > 1 ? deg : 1);
        float logd = logf(degc + 1.f);
        g_s1[i] = logd / AVG_LOG_C;
        g_s2[i] = AVG_LOG_C / logd;
    }
}

// ---------------- per-node segmented aggregation (warp per node) ----------------
template <int F>
__global__ void __launch_bounds__(256) k_agg(const float* __restrict__ H) {
    constexpr int FPT = F / 32;
    int wid = (blockIdx.x * 256 + threadIdx.x) >> 5;
    int lane = threadIdx.x & 31;
    if (wid >= NN) return;
    int n = wid;
    int deg = g_cnt[n];
    int st = g_rowstart[n];
    float sum[FPT], ssq[FPT], mn[FPT], mx[FPT];
#pragma unroll
    for (int i = 0; i < FPT; i++) { sum[i] = 0.f; ssq[i] = 0.f; mn[i] = 3.4e38f; mx[i] = -3.4e38f; }
    for (int e = 0; e < deg; e++) {
        int s = g_srt[st + e];
        const float* row = H + s * F;
#pragma unroll
        for (int i = 0; i < FPT; i++) {
            float v = row[lane + 32 * i];
            sum[i] += v;
            ssq[i] += v * v;
            mn[i] = fminf(mn[i], v);
            mx[i] = fmaxf(mx[i], v);
        }
    }
    float inv = 1.f / (float)(deg > 1 ? deg : 1);
    float* out = g_agg + n * (4 * F);
#pragma unroll
    for (int i = 0; i < FPT; i++) {
        int f = lane + 32 * i;
        float mean = sum[i] * inv;
        float msq = ssq[i] * inv;
        float sd = sqrtf(fmaxf(msq - mean * mean, 0.f) + 1e-5f);
        float lmn = (deg > 0) ? mn[i] : 0.f;
        float lmx = (deg > 0) ? mx[i] : 0.f;
        out[f] = mean;
        out[F + f] = lmn;
        out[2 * F + f] = lmx;
        out[3 * F + f] = sd;
    }
}

// ---------------- fused PNA GEMM: [x | agg | agg*s1 | agg*s2] @ W + b ----------------
// block: 64 nodes x FO cols, 256 threads, BK=32. A-tiles built on the fly.
template <int F, int FO, int CPT, bool RELU>
__global__ void __launch_bounds__(256) k_gemm(const float* __restrict__ H,
                                              const float* __restrict__ W,
                                              const float* __restrict__ B,
                                              float* __restrict__ OUT) {
    constexpr int K = 13 * F;
    constexpr int FOP = 16 * CPT;  // padded cols
    constexpr int F4 = 4 * F;
    __shared__ float As[64 * 33];
    __shared__ float Ws[32 * FOP];
    int tid = threadIdx.x;
    int ct = tid >> 4;   // 0..15  col group
    int nt = tid & 15;   // 0..15  node group (4 nodes each)
    int n0 = blockIdx.x * 64;
    float acc[4][CPT];
#pragma unroll
    for (int i = 0; i < 4; i++)
#pragma unroll
        for (int j = 0; j < CPT; j++) acc[i][j] = 0.f;

    for (int kt = 0; kt < K; kt += 32) {
        // load W tile (coalesced; zero-pad cols >= FO)
        for (int idx = tid; idx < 32 * FOP; idx += 256) {
            int kk = idx / FOP;
            int c = idx - kk * FOP;
            float v = 0.f;
            if (c < FO) v = W[(kt + kk) * FO + c];
            Ws[kk * FOP + c] = v;
        }
        // build A tile on the fly (coalesced along k)
        for (int idx = tid; idx < 2048; idx += 256) {
            int nl = idx >> 5;
            int kk = idx & 31;
            int n = n0 + nl;
            float v = 0.f;
            if (n < NN) {
                int k = kt + kk;
                if (k < F) {
                    v = H[n * F + k];
                } else {
                    int j = k - F;
                    float sc;
                    int jj;
                    if (j < F4)          { sc = 1.f;     jj = j; }
                    else if (j < 2 * F4) { sc = g_s1[n]; jj = j - F4; }
                    else                 { sc = g_s2[n]; jj = j - 2 * F4; }
                    v = g_agg[n * F4 + jj] * sc;
                }
            }
            As[nl * 33 + kk] = v;
        }
        __syncthreads();
#pragma unroll
        for (int kk = 0; kk < 32; kk++) {
            float a0 = As[(nt * 4 + 0) * 33 + kk];
            float a1 = As[(nt * 4 + 1) * 33 + kk];
            float a2 = As[(nt * 4 + 2) * 33 + kk];
            float a3 = As[(nt * 4 + 3) * 33 + kk];
            float wv[CPT];
#pragma unroll
            for (int j = 0; j < CPT; j += 2) {
                float2 w2 = *(const float2*)&Ws[kk * FOP + ct * CPT + j];
                wv[j] = w2.x;
                wv[j + 1] = w2.y;
            }
#pragma unroll
            for (int j = 0; j < CPT; j++) {
                acc[0][j] = fmaf(a0, wv[j], acc[0][j]);
                acc[1][j] = fmaf(a1, wv[j], acc[1][j]);
                acc[2][j] = fmaf(a2, wv[j], acc[2][j]);
                acc[3][j] = fmaf(a3, wv[j], acc[3][j]);
            }
        }
        __syncthreads();
    }
#pragma unroll
    for (int i = 0; i < 4; i++) {
        int n = n0 + nt * 4 + i;
        if (n < NN) {
#pragma unroll
            for (int j = 0; j < CPT; j++) {
                int c = ct * CPT + j;
                if (c < FO) {
                    float r = acc[i][j] + B[c];
                    if (RELU) r = fmaxf(r, 0.f);
                    OUT[n * FO + c] = r;
                }
            }
        }
    }
}

// ---------------- batchnorm ----------------
__global__ void k_bnzero() {
    int i = threadIdx.x;
    if (i < 128) { g_bnsum[i] = 0.f; g_bnssq[i] = 0.f; }
}

template <int C>
__global__ void k_bnstats(const float* __restrict__ h) {
    int c = threadIdx.x;
    if (c >= C) return;
    float s = 0.f, q = 0.f;
    for (int r = blockIdx.x; r < NN; r += gridDim.x) {
        float v = h[r * C + c];
        s += v;
        q += v * v;
    }
    atomicAdd(&g_bnsum[c], s);
    atomicAdd(&g_bnssq[c], q);
}

template <int C>
__global__ void k_bnfin(const float* __restrict__ g, const float* __restrict__ be) {
    int c = threadIdx.x;
    if (c < C) {
        float mu = g_bnsum[c] / (float)NN;
        float var = g_bnssq[c] / (float)NN - mu * mu;
        float rs = rsqrtf(var + 1e-5f);
        float sc = g[c] * rs;
        g_scale[c] = sc;
        g_shift[c] = be[c] - mu * sc;
    }
}

template <int C, bool RELU>
__global__ void k_bnapply(float* __restrict__ h) {
    int i = blockIdx.x * 256 + threadIdx.x;
    if (i < NN * C) {
        int c = i % C;
        float v = h[i] * g_scale[c] + g_shift[c];
        if (RELU) v = fmaxf(v, 0.f);
        h[i] = v;
    }
}

// ---------------- pooling + head ----------------
__global__ void k_pool(const float* __restrict__ h, const int* __restrict__ batch) {
    int i = blockIdx.x * 256 + threadIdx.x;
    if (i < NN) {
        int g = batch[i];
        atomicAdd(&g_gcnt[g], 1);
        const float* row = h + i * 20;
#pragma unroll
        for (int c = 0; c < 20; c++) {
            float v = row[c] * g_scale[c] + g_shift[c];
            atomicAdd(&g_zsum[g * 20 + c], v);
        }
    }
}

__global__ void k_final(const float* __restrict__ wl, const float* __restrict__ bl,
                        float* __restrict__ out, int out_size) {
    int g = threadIdx.x;
    if (g >= NGR) return;
    float inv = 1.f / fmaxf((float)g_gcnt[g], 1.f);
    float z[20];
#pragma unroll
    for (int c = 0; c < 20; c++) z[c] = g_zsum[g * 20 + c] * inv;
    float lo[11];
    float m = -3.4e38f;
#pragma unroll
    for (int o = 0; o < 11; o++) {
        float a = bl[o];
#pragma unroll
        for (int c = 0; c < 20; c++) a += z[c] * wl[c * 11 + o];
        lo[o] = a;
        m = fmaxf(m, a);
    }
    float ssum = 0.f;
#pragma unroll
    for (int o = 0; o < 11; o++) { lo[o] = expf(lo[o] - m); ssum += lo[o]; }
    float isum = 1.f / ssum;
#pragma unroll
    for (int o = 0; o < 11; o++) {
        int idx = g * 11 + o;
        if (idx < out_size) out[idx] = lo[o] * isum;
    }
#pragma unroll
    for (int c = 0; c < 20; c++) {
        int idx = NGR * 11 + g * 20 + c;
        if (idx < out_size) out[idx] = z[c];
    }
}

// ---------------- launcher ----------------
extern "C" void kernel_launch(void* const* d_in, const int* in_sizes, int n_in,
                              void* d_out, int out_size) {
    const float* x = (const float*)d_in[0];
    const int* ei = (const int*)d_in[1];
    const int* src = ei;
    const int* dst = ei + NE;
    const int* batch = (const int*)d_in[2];
    const float* w0 = (const float*)d_in[3];  const float* b0 = (const float*)d_in[4];
    const float* w1 = (const float*)d_in[5];  const float* b1 = (const float*)d_in[6];
    const float* w2 = (const float*)d_in[7];  const float* b2 = (const float*)d_in[8];
    const float* w3 = (const float*)d_in[9];  const float* b3 = (const float*)d_in[10];
    const float* g0 = (const float*)d_in[11]; const float* be0 = (const float*)d_in[12];
    const float* g1 = (const float*)d_in[13]; const float* be1 = (const float*)d_in[14];
    const float* g2 = (const float*)d_in[15]; const float* be2 = (const float*)d_in[16];
    const float* wl = (const float*)d_in[17]; const float* bl = (const float*)d_in[18];

    void* pA = 0; void* pB = 0;
    cudaGetSymbolAddress(&pA, g_hA);
    cudaGetSymbolAddress(&pB, g_hB);
    float* hA = (float*)pA;
    float* hB = (float*)pB;

    const int GB_E = (NE + 255) / 256;     // 12500
    const int GB_N = (NN + 255) / 256;     // 391
    const int GB_G = (NN + 63) / 64;       // 1563

    k_zero<<<GB_N, 256>>>();
    k_count<<<GB_E, 256>>>(dst);
    k_scan1<<<GB_N, 256>>>();
    k_scan2<<<1, 512>>>();
    k_scan3<<<GB_N, 256>>>();
    k_scatter<<<GB_E, 256>>>(src, dst);
    k_prep<<<GB_N, 256>>>();

    // layer 0: 64 -> 96, BN + relu
    k_agg<64><<<(NN * 32 + 255) / 256, 256>>>(x);
    k_gemm<64, 96, 6, false><<<GB_G, 256>>>(x, w0, b0, hA);
    k_bnzero<<<1, 128>>>();
    k_bnstats<96><<<512, 96>>>(hA);
    k_bnfin<96><<<1, 96>>>(g0, be0);
    k_bnapply<96, true><<<(NN * 96 + 255) / 256, 256>>>(hA);

    // layer 1: 96 -> 64, BN + relu
    k_agg<96><<<(NN * 32 + 255) / 256, 256>>>(hA);
    k_gemm<96, 64, 4, false><<<GB_G, 256>>>(hA, w1, b1, hB);
    k_bnzero<<<1, 128>>>();
    k_bnstats<64><<<512, 64>>>(hB);
    k_bnfin<64><<<1, 64>>>(g1, be1);
    k_bnapply<64, true><<<(NN * 64 + 255) / 256, 256>>>(hB);

    // layer 2: 64 -> 32, relu only (fused into GEMM epilogue)
    k_agg<64><<<(NN * 32 + 255) / 256, 256>>>(hB);
    k_gemm<64, 32, 2, true><<<GB_G, 256>>>(hB, w2, b2, hA);

    // layer 3: 32 -> 20, BN (affine fused into pooling)
    k_agg<32><<<(NN * 32 + 255) / 256, 256>>>(hA);
    k_gemm<32, 20, 2, false><<<GB_G, 256>>>(hA, w3, b3, hB);
    k_bnzero<<<1, 128>>>();
    k_bnstats<20><<<512, 32>>>(hB);
    k_bnfin<20><<<1, 32>>>(g2, be2);

    k_pool<<<GB_N, 256>>>(hB, batch);
    k_final<<<1, 64>>>(wl, bl, (float*)d_out, out_size);
}